// round 11
// baseline (speedup 1.0000x reference)
#include <cuda_runtime.h>
#include <cuda_fp16.h>
#include <cstdint>

// SpatialDeformer3D: trilinear warp of X[...,0] by per-voxel deformation.
// Shapes fixed: B=2, H=160, W=192, D=160.
//
// R10 = R9 resubmit (infra failure last round), hardened:
//  - R8 core: parity-duplicated fp16 volume, half2 z-pair gathers (4 LDG/vox)
//  - def staged per-block via ONE cp.async.bulk (6144 B) through the TMA pipe
//    (zero L1tex wavefronts) + conflict-free LDS.64 reads
//  - suspend-time try_wait loop; bulk copy issued before index math

namespace {
constexpr int B  = 2;
constexpr int H  = 160;
constexpr int W  = 192;
constexpr int D  = 160;
constexpr int WD = W * D;            // 30720
constexpr int N  = H * W * D;        // 4,915,200 per batch
constexpr int NT = B * N;            // 9,830,400 total voxels
constexpr int PRE_ITEMS = NT / 8;
constexpr int THREADS   = 256;
constexpr int VOX_PER_BLOCK = THREADS * 2;          // 512
constexpr int DEF_BYTES = VOX_PER_BLOCK * 3 * 4;    // 6144 B per block
}

// Two fp16 copies of X channel-0, 19.7 MB each. Static scratch (no allocs).
__device__ __half g_even[NT];
__device__ __half g_odd[NT];

// ---------------------------------------------------------------------------
// Pre-pass: X interleaved f32 (ch0,ch1) -> g_even (ch0), g_odd (ch0 shifted).
__global__ void __launch_bounds__(256)
compact_kernel(const float4* __restrict__ X4) {
    int i = blockIdx.x * blockDim.x + threadIdx.x;
    if (i >= PRE_ITEMS) return;
    float4 a = X4[4 * i + 0];
    float4 b = X4[4 * i + 1];
    float4 c = X4[4 * i + 2];
    float4 d = X4[4 * i + 3];
    float extra = (i + 1 < PRE_ITEMS) ? X4[4 * i + 4].x : d.z;

    __half2 he[4], ho[4];
    he[0] = __floats2half2_rn(a.x, a.z);
    he[1] = __floats2half2_rn(b.x, b.z);
    he[2] = __floats2half2_rn(c.x, c.z);
    he[3] = __floats2half2_rn(d.x, d.z);
    ho[0] = __floats2half2_rn(a.z, b.x);
    ho[1] = __floats2half2_rn(b.z, c.x);
    ho[2] = __floats2half2_rn(c.z, d.x);
    ho[3] = __floats2half2_rn(d.z, extra);

    reinterpret_cast<uint4*>(g_even)[i] = *reinterpret_cast<uint4*>(he);
    reinterpret_cast<uint4*>(g_odd)[i]  = *reinterpret_cast<uint4*>(ho);
}

// ---------------------------------------------------------------------------
__device__ __forceinline__ float clampi_f(int v, int hi, int* out_i) {
    int c = v < 0 ? 0 : (v > hi ? hi : v);
    *out_i = c;
    return (float)c;
}

__device__ __forceinline__ float sample_one(int bN, int ix, int iy, int iz,
                                            float dx, float dy, float dz) {
    float x = (float)ix + dx;
    float y = (float)iy + dy;
    float z = (float)iz + dz;

    int x0i = (int)floorf(x);
    int y0i = (int)floorf(y);
    int z0i = (int)floorf(z);

    int x0, x1, y0, y1;
    float x0f = clampi_f(x0i,     W - 1, &x0);
    float x1f = clampi_f(x0i + 1, W - 1, &x1);
    float y0f = clampi_f(y0i,     H - 1, &y0);
    float y1f = clampi_f(y0i + 1, H - 1, &y1);
    float wx0 = x - x0f, wx1 = x1f - x;
    float wy0 = y - y0f, wy1 = y1f - y;

    // z degenerate (floor outside [0,D-2]) contributes exactly 0 in the ref
    // (wz0+wz1 = z1f-z0f = 0) -> zero the z-weights explicitly.
    bool zok  = (z0i >= 0) && (z0i < D - 1);
    int  zz   = zok ? z0i : 0;
    float wz0 = zok ? (z - (float)z0i)        : 0.0f;
    float wz1 = zok ? ((float)z0i + 1.0f - z) : 0.0f;

    const __half2* gz = (zz & 1) ? reinterpret_cast<const __half2*>(g_odd)
                                 : reinterpret_cast<const __half2*>(g_even);

    int i00 = bN + y0 * WD + x0 * D;
    int i01 = bN + y0 * WD + x1 * D;
    int i10 = bN + y1 * WD + x0 * D;
    int i11 = bN + y1 * WD + x1 * D;

    __half2 h00 = __ldg(&gz[(i00 + zz) >> 1]);   // .x=[z0], .y=[z0+1]
    __half2 h01 = __ldg(&gz[(i01 + zz) >> 1]);
    __half2 h10 = __ldg(&gz[(i10 + zz) >> 1]);
    __half2 h11 = __ldg(&gz[(i11 + zz) >> 1]);

    float c00 = wz1 * __half2float(h00.x) + wz0 * __half2float(h00.y);
    float c01 = wz1 * __half2float(h01.x) + wz0 * __half2float(h01.y);
    float c10 = wz1 * __half2float(h10.x) + wz0 * __half2float(h10.y);
    float c11 = wz1 * __half2float(h11.x) + wz0 * __half2float(h11.y);

    float c0 = wx1 * c00 + wx0 * c01;
    float c1 = wx1 * c10 + wx0 * c11;

    return wy1 * c0 + wy0 * c1;
}

__global__ void __launch_bounds__(THREADS)
deform3d_kernel(const float* __restrict__ def,
                float2* __restrict__ out2) {
    __shared__ alignas(128) float sdef[VOX_PER_BLOCK * 3];   // 6144 B
    __shared__ alignas(8) unsigned long long mbar;

    int tid = threadIdx.x;

    uint32_t s_def  = (uint32_t)__cvta_generic_to_shared(sdef);
    uint32_t s_mbar = (uint32_t)__cvta_generic_to_shared(&mbar);

    if (tid == 0) {
        asm volatile("mbarrier.init.shared.b64 [%0], 1;" :: "r"(s_mbar) : "memory");
        asm volatile("fence.proxy.async.shared::cta;" ::: "memory");
    }
    __syncthreads();

    if (tid == 0) {
        const float* src = def + (size_t)blockIdx.x * (VOX_PER_BLOCK * 3);
        asm volatile("mbarrier.arrive.expect_tx.shared.b64 _, [%0], %1;"
                     :: "r"(s_mbar), "r"(DEF_BYTES) : "memory");
        asm volatile(
            "cp.async.bulk.shared::cluster.global.mbarrier::complete_tx::bytes "
            "[%0], [%1], %2, [%3];"
            :: "r"(s_def), "l"(src), "r"(DEF_BYTES), "r"(s_mbar) : "memory");
    }

    // Overlap index math with the in-flight TMA copy.
    int t   = blockIdx.x * THREADS + tid;   // [0, NT/2), grid exact
    int r2  = t * 2;
    int b   = r2 / N;
    int r   = r2 - b * N;
    int iy  = r / WD;
    int rem = r - iy * WD;
    int ix  = rem / D;
    int iz  = rem - ix * D;                 // even; iz+1 < D
    int bN  = b * N;

    // Wait (phase 0), acquire, with HW suspend-time hint (no hot spin).
    asm volatile(
        "{\n\t"
        ".reg .pred p;\n\t"
        "WAIT_%=:\n\t"
        "mbarrier.try_wait.parity.acquire.cta.shared::cta.b64 p, [%0], 0, 0x989680;\n\t"
        "@!p bra WAIT_%=;\n\t"
        "}"
        :: "r"(s_mbar) : "memory");

    // 6 def floats for this thread's voxel pair (width-limited, conflict-free).
    const float2* sdef2 = reinterpret_cast<const float2*>(sdef);
    float2 d0 = sdef2[3 * tid + 0];   // (dxA, dyA)
    float2 d1 = sdef2[3 * tid + 1];   // (dzA, dxB)
    float2 d2 = sdef2[3 * tid + 2];   // (dyB, dzB)

    float2 o;
    o.x = sample_one(bN, ix, iy, iz,     d0.x, d0.y, d1.x);
    o.y = sample_one(bN, ix, iy, iz + 1, d1.y, d2.x, d2.y);

    __stcs(&out2[t], o);
}

extern "C" void kernel_launch(void* const* d_in, const int* in_sizes, int n_in,
                              void* d_out, int out_size) {
    const float* X   = (const float*)d_in[0];
    const float* def = (const float*)d_in[1];

    constexpr int pre_blocks  = (PRE_ITEMS + 255) / 256;    // 4800
    constexpr int main_blocks = NT / VOX_PER_BLOCK;         // 19200 exact

    compact_kernel<<<pre_blocks, 256>>>(reinterpret_cast<const float4*>(X));
    deform3d_kernel<<<main_blocks, THREADS>>>(
        def, reinterpret_cast<float2*>(d_out));
}